// round 1
// baseline (speedup 1.0000x reference)
#include <cuda_runtime.h>
#include <cstdint>

#define M_ATOMS 9216
#define L_RES   256
#define A_ATOM  36
#define K_NB    24
#define D0      64
#define KC      3
#define EDGEDIM 32
#define HEADS   4
#define DHD     16
#define RBF_N   16
#define MAXB    4
#define KIN_DIM 99
#define KIN_PAD 100
#define QIN_DIM 67
#define OUTC    144   /* 64 (k) + 64 (v0) + 16 (v1) */
#define BIGF    1e9f
#define EPSF    1e-5f

// ---------------- device scratch (no allocations allowed) ----------------
__device__ int           g_nM;
__device__ int           g_midx[M_ATOMS];
__device__ float4        g_cxyz[M_ATOMS];          // xyz of masked atoms, w = atom index (bits)
__device__ unsigned char g_maskf[M_ATOMS];
__device__ int           g_knn[M_ATOMS * K_NB];
__device__ float         g_WT[OUTC * KIN_PAD];     // transposed [Wk|Wv0|Wv1], row d: 99 kk + pad

// ---------------- init output (xyz_new = xyz, state_new = state) ----------------
__global__ void init_out_kernel(const float* __restrict__ xyz,
                                const float* __restrict__ state,
                                float* __restrict__ out) {
    const int total = M_ATOMS * 3 + M_ATOMS * D0;
    for (int i = blockIdx.x * blockDim.x + threadIdx.x; i < total; i += gridDim.x * blockDim.x)
        out[i] = (i < M_ATOMS * 3) ? xyz[i] : state[i - M_ATOMS * 3];
}

// ---------------- transpose weights into g_WT ----------------
__global__ void prep_wt_kernel(const float* __restrict__ Wk,
                               const float* __restrict__ Wv0,
                               const float* __restrict__ Wv1) {
    int idx = blockIdx.x * blockDim.x + threadIdx.x;
    if (idx >= OUTC * KIN_PAD) return;
    int d = idx / KIN_PAD, kk = idx % KIN_PAD;
    float v = 0.f;
    if (kk < KIN_DIM) {
        if (d < 64)       v = Wk [kk * 64 + d];
        else if (d < 128) v = Wv0[kk * 64 + (d - 64)];
        else              v = Wv1[kk * 16 + (d - 128)];
    }
    g_WT[idx] = v;
}

// ---------------- mask + compaction (single block, deterministic scan) ----------------
__global__ void compact_kernel(const int* __restrict__ seq,
                               const float* __restrict__ xyz,
                               const void* __restrict__ aamask) {
    __shared__ int s_scan[1024];
    __shared__ int s_nz_off4;   // any byte at p%4!=0 nonzero
    __shared__ int s_f_ok;      // first 189 words all {0.0f,1.0f}
    __shared__ int s_f_one;     // some word == 1.0f
    int tid = threadIdx.x;
    if (tid == 0) { s_nz_off4 = 0; s_f_ok = 1; s_f_one = 0; }
    __syncthreads();

    const unsigned char* am8  = (const unsigned char*)aamask;
    const int*           am32 = (const int*)aamask;
    const float*         amf  = (const float*)aamask;
    const int NA = 21 * A_ATOM; // 756

    for (int p = tid; p < NA; p += 1024)
        if ((p & 3) && am8[p]) atomicOr(&s_nz_off4, 1);
    for (int wi = tid; wi < NA / 4; wi += 1024) {       // first 189 float words
        float f = amf[wi];
        if (!(f == 0.0f || f == 1.0f)) atomicAnd(&s_f_ok, 0);
        if (f == 1.0f) atomicOr(&s_f_one, 1);
    }
    __syncthreads();
    // mode: 0=int32, 1=uint8/bool, 2=float32
    int mode = (!s_nz_off4) ? 0 : ((s_f_ok && s_f_one) ? 2 : 1);

    int base = tid * 9;
    unsigned char f[9];
    int cnt = 0;
#pragma unroll
    for (int i = 0; i < 9; ++i) {
        int m = base + i;
        int l = m / A_ATOM, a = m % A_ATOM;
        int q = seq[l] * A_ATOM + a;
        int v;
        if (mode == 0)      v = am32[q];
        else if (mode == 1) v = (int)am8[q];
        else                v = (amf[q] != 0.0f);
        f[i] = (v != 0);
        cnt += f[i];
    }
    s_scan[tid] = cnt;
    __syncthreads();
    for (int off = 1; off < 1024; off <<= 1) {
        int v = 0;
        if (tid >= off) v = s_scan[tid - off];
        __syncthreads();
        s_scan[tid] += v;
        __syncthreads();
    }
    int pos = s_scan[tid] - cnt;
#pragma unroll
    for (int i = 0; i < 9; ++i) {
        int m = base + i;
        g_maskf[m] = f[i];
        if (f[i]) {
            g_midx[pos] = m;
            g_cxyz[pos] = make_float4(xyz[m * 3], xyz[m * 3 + 1], xyz[m * 3 + 2],
                                      __int_as_float(m));
            pos++;
        }
    }
    if (tid == 1023) g_nM = s_scan[1023];
}

// ---------------- exact top-24 nearest masked neighbors ----------------
__global__ void __launch_bounds__(256) knn_kernel(const float* __restrict__ xyz) {
    __shared__ float s_d2[M_ATOMS];
    __shared__ unsigned long long s_red[8];
    int m = blockIdx.x;
    if (!g_maskf[m]) return;
    int tid = threadIdx.x;
    int nM = g_nM;
    float px = xyz[m * 3], py = xyz[m * 3 + 1], pz = xyz[m * 3 + 2];

    for (int j = tid; j < nM; j += 256) {
        float4 c = g_cxyz[j];
        float dx = c.x - px, dy = c.y - py, dz = c.z - pz;
        float d2 = dx * dx + dy * dy + dz * dz;
        if (__float_as_int(c.w) == m) d2 = BIGF;   // exclude self
        s_d2[j] = d2;
    }
    __syncthreads();

    int lane = tid & 31, wid = tid >> 5;
    for (int r = 0; r < K_NB; ++r) {
        unsigned long long best = ~0ull;
        for (int j = tid; j < nM; j += 256) {
            unsigned long long c =
                ((unsigned long long)__float_as_uint(s_d2[j]) << 32) | (unsigned)j;
            if (c < best) best = c;
        }
        for (int off = 16; off > 0; off >>= 1) {
            unsigned long long o = __shfl_down_sync(0xffffffffu, best, off);
            if (o < best) best = o;
        }
        if (lane == 0) s_red[wid] = best;
        __syncthreads();
        if (tid == 0) {
            unsigned long long b = s_red[0];
            for (int w = 1; w < 8; ++w) if (s_red[w] < b) b = s_red[w];
            int win = (int)(b & 0xffffffffu);
            float dwin = __uint_as_float((unsigned)(b >> 32));
            g_knn[m * K_NB + r] = (dwin < BIGF * 0.5f) ? g_midx[win] : m;
            s_d2[win] = BIGF;
        }
        __syncthreads();
    }
}

// ---------------- per-atom edge attention ----------------
__global__ void __launch_bounds__(160) attn_kernel(
    const int* __restrict__ seq, const float* __restrict__ xyz,
    const int* __restrict__ num_bonds, const float* __restrict__ state,
    const float* __restrict__ grads,
    const float* __restrict__ We, const float* __restrict__ be,
    const float* __restrict__ Wq,
    const float* __restrict__ Wo0, const float* __restrict__ Wself,
    const float* __restrict__ b0, float* __restrict__ out) {
    int m = blockIdx.x;
    if (!g_maskf[m]) return;
    int tid = threadIdx.x;

    __shared__ float s_kin[K_NB][KIN_PAD];
    __shared__ float s_kv[K_NB][145];
    __shared__ float s_q[64];
    __shared__ float s_node[64];
    __shared__ float s_norm[KC];
    __shared__ float s_dirv[K_NB][3];
    __shared__ float s_l1j[K_NB][KC][3];
    __shared__ float s_eraw[K_NB][21];
    __shared__ float s_logit[HEADS][K_NB];
    __shared__ float s_attn[HEADS][K_NB];
    __shared__ float s_o0[64];
    __shared__ float s_coef[K_NB][4];
    __shared__ float s_vm[K_NB][3];
    __shared__ int   s_idx[K_NB];
    __shared__ float s_ok[K_NB];

    // ---- phase 0: own node, norms, edge geometry ----
    for (int d = tid; d < 64; d += 160) s_node[d] = state[m * 64 + d];
    if (tid >= 64 && tid < 64 + KC) {
        int c = tid - 64;
        float s = EPSF;
#pragma unroll
        for (int dd = 0; dd < 3; ++dd) {
            float v = grads[(c * M_ATOMS + m) * 3 + dd];
            s = fmaf(v, v, s);
        }
        s_norm[c] = sqrtf(s);
    }
    if (tid < K_NB) {
        int e = tid;
        int j = g_knn[m * K_NB + e];
        s_idx[e] = j;
        float rx = xyz[j * 3]     - xyz[m * 3];
        float ry = xyz[j * 3 + 1] - xyz[m * 3 + 1];
        float rz = xyz[j * 3 + 2] - xyz[m * 3 + 2];
        float d2 = rx * rx + ry * ry + rz * rz;
        float dist = sqrtf(d2 + EPSF);
        float inv_d = 1.f / dist;
        float dvx = rx * inv_d, dvy = ry * inv_d, dvz = rz * inv_d;
        s_dirv[e][0] = dvx; s_dirv[e][1] = dvy; s_dirv[e][2] = dvz;
        s_ok[e] = (j != m) ? 1.f : 0.f;
#pragma unroll
        for (int c = 0; c < KC; ++c) {
            float lx = grads[(c * M_ATOMS + j) * 3 + 0];
            float ly = grads[(c * M_ATOMS + j) * 3 + 1];
            float lz = grads[(c * M_ATOMS + j) * 3 + 2];
            s_l1j[e][c][0] = lx; s_l1j[e][c][1] = ly; s_l1j[e][c][2] = lz;
            s_kin[e][96 + c] = lx * dvx + ly * dvy + lz * dvz;   // invariants
        }
        s_kin[e][99] = 0.f;
        int ri = m / A_ATOM, ai = m % A_ATOM;
        int rj = j / A_ATOM, aj = j % A_ATOM;
        int b = 0;
        if (rj == ri) b = num_bonds[(seq[ri] * A_ATOM + ai) * A_ATOM + aj];
        b = min(max(b, 0), MAXB);
#pragma unroll
        for (int t = 0; t < RBF_N; ++t) {
            float mu = 0.4f * (float)t;                          // linspace(0,6,16)
            float r = dist - mu;
            s_eraw[e][t] = expf(-2.f * r * r);                   // SIG = 0.5
        }
#pragma unroll
        for (int t = 0; t <= MAXB; ++t) s_eraw[e][RBF_N + t] = (t == b) ? 1.f : 0.f;
    }
    __syncthreads();

    // ---- phase 1: build kin rows, q ----
    for (int idx = tid; idx < K_NB * 64; idx += 160) {
        int e = idx >> 6, d = idx & 63;
        s_kin[e][d] = state[s_idx[e] * 64 + d];
    }
    for (int idx = tid; idx < K_NB * EDGEDIM; idx += 160) {
        int e = idx >> 5, c = idx & 31;
        float acc = be[c];
#pragma unroll
        for (int kk = 0; kk < 21; ++kk)
            acc = fmaf(s_eraw[e][kk], We[kk * EDGEDIM + c], acc);
        s_kin[e][64 + c] = acc;
    }
    if (tid < 64) {
        float acc = 0.f;
        for (int kk = 0; kk < 64; ++kk)
            acc = fmaf(s_node[kk], Wq[kk * 64 + tid], acc);
#pragma unroll
        for (int c = 0; c < KC; ++c)
            acc = fmaf(s_norm[c], Wq[(64 + c) * 64 + tid], acc);
        s_q[tid] = acc;
    }
    __syncthreads();

    // ---- phase 2: main GEMM  kin[24x99] @ WT -> k|v0|v1 [24x144] ----
    if (tid < OUTC) {
        float acc[K_NB];
#pragma unroll
        for (int e = 0; e < K_NB; ++e) acc[e] = 0.f;
        const float4* wrow = (const float4*)(g_WT + tid * KIN_PAD);
        for (int g = 0; g < KIN_PAD / 4; ++g) {
            float4 w = wrow[g];
#pragma unroll
            for (int e = 0; e < K_NB; ++e) {
                float4 kv = *(const float4*)&s_kin[e][4 * g];
                acc[e] = fmaf(kv.x, w.x, acc[e]);
                acc[e] = fmaf(kv.y, w.y, acc[e]);
                acc[e] = fmaf(kv.z, w.z, acc[e]);
                acc[e] = fmaf(kv.w, w.w, acc[e]);
            }
        }
#pragma unroll
        for (int e = 0; e < K_NB; ++e) s_kv[e][tid] = acc[e];
    }
    __syncthreads();

    // ---- phase 3: logits ----
    if (tid < HEADS * K_NB) {
        int h = tid / K_NB, e = tid % K_NB;
        float acc = 0.f;
#pragma unroll
        for (int dh = 0; dh < DHD; ++dh)
            acc = fmaf(s_q[h * DHD + dh], s_kv[e][h * DHD + dh], acc);
        s_logit[h][e] = (s_ok[e] > 0.f) ? acc * 0.25f : -1e9f;
    }
    __syncthreads();

    // ---- phase 4: softmax (warp h handles head h) ----
    {
        int w = tid >> 5, lane = tid & 31;
        if (w < HEADS) {
            float v = (lane < K_NB) ? s_logit[w][lane] : -1e30f;
            float mx = v;
            for (int off = 16; off > 0; off >>= 1)
                mx = fmaxf(mx, __shfl_xor_sync(0xffffffffu, mx, off));
            float ex = (lane < K_NB) ? expf(v - mx) : 0.f;
            float sm = ex;
            for (int off = 16; off > 0; off >>= 1)
                sm += __shfl_xor_sync(0xffffffffu, sm, off);
            if (lane < K_NB) s_attn[w][lane] = ex / sm;
        }
    }
    __syncthreads();

    // ---- phase 5: o0, coef ----
    if (tid < 64) {
        int h = tid >> 4;
        float acc = 0.f;
#pragma unroll
        for (int e = 0; e < K_NB; ++e)
            acc = fmaf(s_attn[h][e], s_kv[e][64 + tid], acc);
        s_o0[tid] = acc;
    } else if (tid < 160) {
        int t = tid - 64;               // 0..95
        int e = t % K_NB, c = t / K_NB; // c < 4
        float acc = 0.f;
#pragma unroll
        for (int h = 0; h < HEADS; ++h)
            acc = fmaf(s_attn[h][e], s_kv[e][128 + h * 4 + c], acc);
        s_coef[e][c] = acc;
    }
    __syncthreads();

    // ---- phase 6: out0 (state), vmsg ----
    if (tid < 64) {
        float acc = b0[tid];
        for (int i = 0; i < 64; ++i) {
            acc = fmaf(s_o0[i],   Wo0[i * 64 + tid],   acc);
            acc = fmaf(s_node[i], Wself[i * 64 + tid], acc);
        }
        out[M_ATOMS * 3 + m * 64 + tid] = acc;
    }
    if (tid >= 64 && tid < 64 + K_NB) {
        int e = tid - 64;
        float c0 = s_coef[e][0];
#pragma unroll
        for (int dd = 0; dd < 3; ++dd) {
            float v = c0 * s_dirv[e][dd];
#pragma unroll
            for (int c = 0; c < KC; ++c)
                v = fmaf(s_coef[e][c + 1], s_l1j[e][c][dd], v);
            s_vm[e][dd] = v;
        }
    }
    __syncthreads();

    // ---- phase 7: out1 (xyz shift) ----
    if (tid < 3) {
        float acc = 0.f;
#pragma unroll
        for (int e = 0; e < K_NB; ++e) acc += s_vm[e][tid];
        out[m * 3 + tid] = xyz[m * 3 + tid] + acc * 0.01f;
    }
}

// ---------------- launch ----------------
extern "C" void kernel_launch(void* const* d_in, const int* in_sizes, int n_in,
                              void* d_out, int out_size) {
    const int*   seq       = (const int*)d_in[0];
    const float* xyz       = (const float*)d_in[1];
    const void*  aamask    = d_in[2];
    const int*   num_bonds = (const int*)d_in[3];
    const float* state     = (const float*)d_in[4];
    const float* grads     = (const float*)d_in[5];
    int w = 6;
    if (n_in >= 16 && in_sizes[6] == 1) w = 7;  // top_k passed as size-1 buffer
    const float* We    = (const float*)d_in[w + 0];
    const float* be    = (const float*)d_in[w + 1];
    const float* Wq    = (const float*)d_in[w + 2];
    const float* Wk    = (const float*)d_in[w + 3];
    const float* Wv0   = (const float*)d_in[w + 4];
    const float* Wv1   = (const float*)d_in[w + 5];
    const float* Wo0   = (const float*)d_in[w + 6];
    const float* Wself = (const float*)d_in[w + 7];
    const float* b0    = (const float*)d_in[w + 8];
    float* out = (float*)d_out;

    init_out_kernel<<<512, 256>>>(xyz, state, out);
    prep_wt_kernel<<<(OUTC * KIN_PAD + 255) / 256, 256>>>(Wk, Wv0, Wv1);
    compact_kernel<<<1, 1024>>>(seq, xyz, aamask);
    knn_kernel<<<M_ATOMS, 256>>>(xyz);
    attn_kernel<<<M_ATOMS, 160>>>(seq, xyz, num_bonds, state, grads,
                                  We, be, Wq, Wo0, Wself, b0, out);
}

// round 2
// speedup vs baseline: 1.6434x; 1.6434x over previous
#include <cuda_runtime.h>
#include <cstdint>

#define M_ATOMS 9216
#define L_RES   256
#define A_ATOM  36
#define K_NB    24
#define D0      64
#define KC      3
#define EDGEDIM 32
#define HEADS   4
#define DHD     16
#define RBF_N   16
#define MAXB    4
#define KIN_DIM 99
#define KIN_PAD 100
#define OUTC    144   /* 64 (k) + 64 (v0) + 16 (v1) */
#define BIGF    1e9f
#define EPSF    1e-5f
#define FULLW   0xffffffffu

// ---------------- device scratch (no allocations allowed) ----------------
__device__ int           g_nM;
__device__ int           g_midx[M_ATOMS];
__device__ float4        g_cxyz[M_ATOMS];          // xyz of masked atoms, w = atom index (bits)
__device__ unsigned char g_maskf[M_ATOMS];
__device__ int           g_knn[M_ATOMS * K_NB];
__device__ float         g_WT[KIN_PAD * OUTC];     // [kk][d] layout: coalesced for GEMM

// ---------------- init output (xyz_new = xyz, state_new = state) ----------------
__global__ void init_out_kernel(const float* __restrict__ xyz,
                                const float* __restrict__ state,
                                float* __restrict__ out) {
    const int total = M_ATOMS * 3 + M_ATOMS * D0;
    for (int i = blockIdx.x * blockDim.x + threadIdx.x; i < total; i += gridDim.x * blockDim.x)
        out[i] = (i < M_ATOMS * 3) ? xyz[i] : state[i - M_ATOMS * 3];
}

// ---------------- transpose weights into g_WT [kk][144] ----------------
__global__ void prep_wt_kernel(const float* __restrict__ Wk,
                               const float* __restrict__ Wv0,
                               const float* __restrict__ Wv1) {
    int idx = blockIdx.x * blockDim.x + threadIdx.x;
    if (idx >= KIN_PAD * OUTC) return;
    int kk = idx / OUTC, d = idx % OUTC;
    float v = 0.f;
    if (kk < KIN_DIM) {
        if (d < 64)       v = Wk [kk * 64 + d];
        else if (d < 128) v = Wv0[kk * 64 + (d - 64)];
        else              v = Wv1[kk * 16 + (d - 128)];
    }
    g_WT[idx] = v;
}

// ---------------- mask + compaction (single block, deterministic scan) ----------------
__global__ void compact_kernel(const int* __restrict__ seq,
                               const float* __restrict__ xyz,
                               const void* __restrict__ aamask) {
    __shared__ int s_scan[1024];
    __shared__ int s_nz_off4;
    __shared__ int s_f_ok;
    __shared__ int s_f_one;
    int tid = threadIdx.x;
    if (tid == 0) { s_nz_off4 = 0; s_f_ok = 1; s_f_one = 0; }
    __syncthreads();

    const unsigned char* am8  = (const unsigned char*)aamask;
    const int*           am32 = (const int*)aamask;
    const float*         amf  = (const float*)aamask;
    const int NA = 21 * A_ATOM; // 756

    for (int p = tid; p < NA; p += 1024)
        if ((p & 3) && am8[p]) atomicOr(&s_nz_off4, 1);
    for (int wi = tid; wi < NA / 4; wi += 1024) {
        float f = amf[wi];
        if (!(f == 0.0f || f == 1.0f)) atomicAnd(&s_f_ok, 0);
        if (f == 1.0f) atomicOr(&s_f_one, 1);
    }
    __syncthreads();
    int mode = (!s_nz_off4) ? 0 : ((s_f_ok && s_f_one) ? 2 : 1);

    int base = tid * 9;
    unsigned char f[9];
    int cnt = 0;
#pragma unroll
    for (int i = 0; i < 9; ++i) {
        int m = base + i;
        int l = m / A_ATOM, a = m % A_ATOM;
        int q = seq[l] * A_ATOM + a;
        int v;
        if (mode == 0)      v = am32[q];
        else if (mode == 1) v = (int)am8[q];
        else                v = (amf[q] != 0.0f);
        f[i] = (v != 0);
        cnt += f[i];
    }
    s_scan[tid] = cnt;
    __syncthreads();
    for (int off = 1; off < 1024; off <<= 1) {
        int v = 0;
        if (tid >= off) v = s_scan[tid - off];
        __syncthreads();
        s_scan[tid] += v;
        __syncthreads();
    }
    int pos = s_scan[tid] - cnt;
#pragma unroll
    for (int i = 0; i < 9; ++i) {
        int m = base + i;
        g_maskf[m] = f[i];
        if (f[i]) {
            g_midx[pos] = m;
            g_cxyz[pos] = make_float4(xyz[m * 3], xyz[m * 3 + 1], xyz[m * 3 + 2],
                                      __int_as_float(m));
            pos++;
        }
    }
    if (tid == 1023) g_nM = s_scan[1023];
}

// ---------------- exact top-24: warp-per-query, one-pass ballot insert ----------------
__global__ void __launch_bounds__(128) knn_kernel(void) {
    __shared__ float s_d[4][K_NB];
    __shared__ int   s_i[4][K_NB];
    int w    = threadIdx.x >> 5;
    int lane = threadIdx.x & 31;
    int qi   = blockIdx.x * 4 + w;
    int nM   = g_nM;
    if (qi >= nM) return;
    int m = g_midx[qi];
    float4 me = g_cxyz[qi];

    if (lane < K_NB) { s_d[w][lane] = BIGF; s_i[w][lane] = -1; }
    __syncwarp();
    float worst = BIGF;
    int   wslot = 0;

    for (int j0 = 0; j0 < nM; j0 += 32) {
        int j = j0 + lane;
        float d2 = BIGF;
        if (j < nM && j != qi) {
            float4 c = g_cxyz[j];
            float dx = c.x - me.x, dy = c.y - me.y, dz = c.z - me.z;
            d2 = dx * dx + dy * dy + dz * dz;
        }
        unsigned ball = __ballot_sync(FULLW, d2 < worst);
        while (ball) {
            int src = __ffs(ball) - 1;
            ball &= ball - 1;
            float dc = __shfl_sync(FULLW, d2, src);
            int   jc = __shfl_sync(FULLW, j,  src);
            if (dc < worst) {
                if (lane == 0) { s_d[w][wslot] = dc; s_i[w][wslot] = jc; }
                __syncwarp();
                float v = (lane < K_NB) ? s_d[w][lane] : -1.0f;
                int   sl = lane;
#pragma unroll
                for (int off = 16; off; off >>= 1) {
                    float ov = __shfl_xor_sync(FULLW, v, off);
                    int   os = __shfl_xor_sync(FULLW, sl, off);
                    if (ov > v) { v = ov; sl = os; }
                }
                worst = v; wslot = sl;
            }
        }
    }
    __syncwarp();
    if (lane < K_NB) {
        float d = s_d[w][lane];
        int   c = s_i[w][lane];
        g_knn[m * K_NB + lane] = (d < BIGF * 0.5f && c >= 0) ? g_midx[c] : m;
    }
}

// ---------------- per-atom edge attention ----------------
__global__ void __launch_bounds__(160) attn_kernel(
    const int* __restrict__ seq, const float* __restrict__ xyz,
    const int* __restrict__ num_bonds, const float* __restrict__ state,
    const float* __restrict__ grads,
    const float* __restrict__ We, const float* __restrict__ be,
    const float* __restrict__ Wq,
    const float* __restrict__ Wo0, const float* __restrict__ Wself,
    const float* __restrict__ b0, float* __restrict__ out) {
    if (blockIdx.x >= g_nM) return;
    int m = g_midx[blockIdx.x];
    int tid = threadIdx.x;

    __shared__ float s_kin[K_NB][KIN_PAD];
    __shared__ float s_kv[K_NB][145];
    __shared__ float s_q[64];
    __shared__ float s_node[64];
    __shared__ float s_norm[KC];
    __shared__ float s_dirv[K_NB][3];
    __shared__ float s_l1j[K_NB][KC][3];
    __shared__ float s_eraw[K_NB][21];
    __shared__ float s_logit[HEADS][K_NB];
    __shared__ float s_attn[HEADS][K_NB];
    __shared__ float s_o0[64];
    __shared__ float s_coef[K_NB][4];
    __shared__ float s_vm[K_NB][3];
    __shared__ int   s_idx[K_NB];
    __shared__ float s_ok[K_NB];

    // ---- phase 0: own node, norms, edge geometry ----
    for (int d = tid; d < 64; d += 160) s_node[d] = state[m * 64 + d];
    if (tid >= 64 && tid < 64 + KC) {
        int c = tid - 64;
        float s = EPSF;
#pragma unroll
        for (int dd = 0; dd < 3; ++dd) {
            float v = grads[(c * M_ATOMS + m) * 3 + dd];
            s = fmaf(v, v, s);
        }
        s_norm[c] = sqrtf(s);
    }
    if (tid < K_NB) {
        int e = tid;
        int j = g_knn[m * K_NB + e];
        s_idx[e] = j;
        float rx = xyz[j * 3]     - xyz[m * 3];
        float ry = xyz[j * 3 + 1] - xyz[m * 3 + 1];
        float rz = xyz[j * 3 + 2] - xyz[m * 3 + 2];
        float d2 = rx * rx + ry * ry + rz * rz;
        float dist = sqrtf(d2 + EPSF);
        float inv_d = 1.f / dist;
        float dvx = rx * inv_d, dvy = ry * inv_d, dvz = rz * inv_d;
        s_dirv[e][0] = dvx; s_dirv[e][1] = dvy; s_dirv[e][2] = dvz;
        s_ok[e] = (j != m) ? 1.f : 0.f;
#pragma unroll
        for (int c = 0; c < KC; ++c) {
            float lx = grads[(c * M_ATOMS + j) * 3 + 0];
            float ly = grads[(c * M_ATOMS + j) * 3 + 1];
            float lz = grads[(c * M_ATOMS + j) * 3 + 2];
            s_l1j[e][c][0] = lx; s_l1j[e][c][1] = ly; s_l1j[e][c][2] = lz;
            s_kin[e][96 + c] = lx * dvx + ly * dvy + lz * dvz;
        }
        s_kin[e][99] = 0.f;
        int ri = m / A_ATOM, ai = m % A_ATOM;
        int rj = j / A_ATOM, aj = j % A_ATOM;
        int b = 0;
        if (rj == ri) b = num_bonds[(seq[ri] * A_ATOM + ai) * A_ATOM + aj];
        b = min(max(b, 0), MAXB);
#pragma unroll
        for (int t = 0; t < RBF_N; ++t) {
            float mu = 0.4f * (float)t;
            float r = dist - mu;
            s_eraw[e][t] = expf(-2.f * r * r);
        }
#pragma unroll
        for (int t = 0; t <= MAXB; ++t) s_eraw[e][RBF_N + t] = (t == b) ? 1.f : 0.f;
    }
    __syncthreads();

    // ---- phase 1: build kin rows, q ----
    for (int idx = tid; idx < K_NB * 64; idx += 160) {
        int e = idx >> 6, d = idx & 63;
        s_kin[e][d] = state[s_idx[e] * 64 + d];
    }
    for (int idx = tid; idx < K_NB * EDGEDIM; idx += 160) {
        int e = idx >> 5, c = idx & 31;
        float acc = be[c];
#pragma unroll
        for (int kk = 0; kk < 21; ++kk)
            acc = fmaf(s_eraw[e][kk], We[kk * EDGEDIM + c], acc);
        s_kin[e][64 + c] = acc;
    }
    if (tid < 64) {
        float acc = 0.f;
        for (int kk = 0; kk < 64; ++kk)
            acc = fmaf(s_node[kk], Wq[kk * 64 + tid], acc);
#pragma unroll
        for (int c = 0; c < KC; ++c)
            acc = fmaf(s_norm[c], Wq[(64 + c) * 64 + tid], acc);
        s_q[tid] = acc;
    }
    __syncthreads();

    // ---- phase 2: GEMM kin[24x100] @ WT[100x144] -> s_kv[24x144] ----
    // weights coalesced across lanes; kin broadcast from shared (1 LDS.128 per 4 FMA)
    if (tid < OUTC) {
        float acc[K_NB];
#pragma unroll
        for (int e = 0; e < K_NB; ++e) acc[e] = 0.f;
        for (int g = 0; g < KIN_PAD / 4; ++g) {
            const float* wp = g_WT + (4 * g) * OUTC + tid;
            float w0 = wp[0];
            float w1 = wp[OUTC];
            float w2 = wp[2 * OUTC];
            float w3 = wp[3 * OUTC];
#pragma unroll
            for (int e = 0; e < K_NB; ++e) {
                float4 kv = *(const float4*)&s_kin[e][4 * g];
                acc[e] = fmaf(kv.x, w0, acc[e]);
                acc[e] = fmaf(kv.y, w1, acc[e]);
                acc[e] = fmaf(kv.z, w2, acc[e]);
                acc[e] = fmaf(kv.w, w3, acc[e]);
            }
        }
#pragma unroll
        for (int e = 0; e < K_NB; ++e) s_kv[e][tid] = acc[e];
    }
    __syncthreads();

    // ---- phase 3: logits ----
    if (tid < HEADS * K_NB) {
        int h = tid / K_NB, e = tid % K_NB;
        float acc = 0.f;
#pragma unroll
        for (int dh = 0; dh < DHD; ++dh)
            acc = fmaf(s_q[h * DHD + dh], s_kv[e][h * DHD + dh], acc);
        s_logit[h][e] = (s_ok[e] > 0.f) ? acc * 0.25f : -1e9f;
    }
    __syncthreads();

    // ---- phase 4: softmax (warp h handles head h) ----
    {
        int w = tid >> 5, lane = tid & 31;
        if (w < HEADS) {
            float v = (lane < K_NB) ? s_logit[w][lane] : -1e30f;
            float mx = v;
            for (int off = 16; off > 0; off >>= 1)
                mx = fmaxf(mx, __shfl_xor_sync(FULLW, mx, off));
            float ex = (lane < K_NB) ? expf(v - mx) : 0.f;
            float sm = ex;
            for (int off = 16; off > 0; off >>= 1)
                sm += __shfl_xor_sync(FULLW, sm, off);
            if (lane < K_NB) s_attn[w][lane] = ex / sm;
        }
    }
    __syncthreads();

    // ---- phase 5: o0, coef ----
    if (tid < 64) {
        int h = tid >> 4;
        float acc = 0.f;
#pragma unroll
        for (int e = 0; e < K_NB; ++e)
            acc = fmaf(s_attn[h][e], s_kv[e][64 + tid], acc);
        s_o0[tid] = acc;
    } else if (tid < 160) {
        int t = tid - 64;
        int e = t % K_NB, c = t / K_NB;
        float acc = 0.f;
#pragma unroll
        for (int h = 0; h < HEADS; ++h)
            acc = fmaf(s_attn[h][e], s_kv[e][128 + h * 4 + c], acc);
        s_coef[e][c] = acc;
    }
    __syncthreads();

    // ---- phase 6: out0 (state), vmsg ----
    if (tid < 64) {
        float acc = b0[tid];
        for (int i = 0; i < 64; ++i) {
            acc = fmaf(s_o0[i],   Wo0[i * 64 + tid],   acc);
            acc = fmaf(s_node[i], Wself[i * 64 + tid], acc);
        }
        out[M_ATOMS * 3 + m * 64 + tid] = acc;
    }
    if (tid >= 64 && tid < 64 + K_NB) {
        int e = tid - 64;
        float c0 = s_coef[e][0];
#pragma unroll
        for (int dd = 0; dd < 3; ++dd) {
            float v = c0 * s_dirv[e][dd];
#pragma unroll
            for (int c = 0; c < KC; ++c)
                v = fmaf(s_coef[e][c + 1], s_l1j[e][c][dd], v);
            s_vm[e][dd] = v;
        }
    }
    __syncthreads();

    // ---- phase 7: out1 (xyz shift) ----
    if (tid < 3) {
        float acc = 0.f;
#pragma unroll
        for (int e = 0; e < K_NB; ++e) acc += s_vm[e][tid];
        out[m * 3 + tid] = xyz[m * 3 + tid] + acc * 0.01f;
    }
}

// ---------------- launch ----------------
extern "C" void kernel_launch(void* const* d_in, const int* in_sizes, int n_in,
                              void* d_out, int out_size) {
    const int*   seq       = (const int*)d_in[0];
    const float* xyz       = (const float*)d_in[1];
    const void*  aamask    = d_in[2];
    const int*   num_bonds = (const int*)d_in[3];
    const float* state     = (const float*)d_in[4];
    const float* grads     = (const float*)d_in[5];
    int w = 6;
    if (n_in >= 16 && in_sizes[6] == 1) w = 7;
    const float* We    = (const float*)d_in[w + 0];
    const float* be    = (const float*)d_in[w + 1];
    const float* Wq    = (const float*)d_in[w + 2];
    const float* Wk    = (const float*)d_in[w + 3];
    const float* Wv0   = (const float*)d_in[w + 4];
    const float* Wv1   = (const float*)d_in[w + 5];
    const float* Wo0   = (const float*)d_in[w + 6];
    const float* Wself = (const float*)d_in[w + 7];
    const float* b0    = (const float*)d_in[w + 8];
    float* out = (float*)d_out;

    init_out_kernel<<<512, 256>>>(xyz, state, out);
    prep_wt_kernel<<<(KIN_PAD * OUTC + 255) / 256, 256>>>(Wk, Wv0, Wv1);
    compact_kernel<<<1, 1024>>>(seq, xyz, aamask);
    knn_kernel<<<(M_ATOMS + 3) / 4, 128>>>();
    attn_kernel<<<M_ATOMS, 160>>>(seq, xyz, num_bonds, state, grads,
                                  We, be, Wq, Wo0, Wself, b0, out);
}

// round 3
// speedup vs baseline: 2.0920x; 1.2730x over previous
#include <cuda_runtime.h>
#include <cstdint>

#define M_ATOMS 9216
#define A_ATOM  36
#define K_NB    24
#define D0      64
#define KC      3
#define HEADS   4
#define DHD     16
#define RBF_N   16
#define MAXB    4
#define KIN_DIM 99
#define OUTC    144   /* 64 (k) + 64 (v0) + 16 (v1) */
#define BIGF    1e9f
#define EPSF    1e-5f
#define FULLW   0xffffffffu
#define KNN_CAP 512

// ---------------- device scratch ----------------
__device__ int           g_nM;
__device__ int           g_midx[M_ATOMS];
__device__ float4        g_cxyz[M_ATOMS];          // xyz of masked atoms, w = atom index (bits)
__device__ int           g_knn[M_ATOMS * K_NB];
__device__ float         g_WT[KIN_DIM * OUTC];     // [kk][144]
__device__ float         g_W2[21 * OUTC];          // We @ W_edge, [21][144]
__device__ float         g_b2[OUTC];               // be @ W_edge
__device__ float         g_P[M_ATOMS * OUTC];      // state @ W_state per atom
__device__ float         g_Qv[M_ATOMS * 64];       // q per atom

// ---------------- init output ----------------
__global__ void init_out_kernel(const float* __restrict__ xyz,
                                const float* __restrict__ state,
                                float* __restrict__ out) {
    const int total = M_ATOMS * 3 + M_ATOMS * D0;
    for (int i = blockIdx.x * blockDim.x + threadIdx.x; i < total; i += gridDim.x * blockDim.x)
        out[i] = (i < M_ATOMS * 3) ? xyz[i] : state[i - M_ATOMS * 3];
}

// ---------------- transpose weights into g_WT [kk][144] ----------------
__global__ void prep_wt_kernel(const float* __restrict__ Wk,
                               const float* __restrict__ Wv0,
                               const float* __restrict__ Wv1) {
    int idx = blockIdx.x * blockDim.x + threadIdx.x;
    if (idx >= KIN_DIM * OUTC) return;
    int kk = idx / OUTC, d = idx % OUTC;
    float v;
    if (d < 64)       v = Wk [kk * 64 + d];
    else if (d < 128) v = Wv0[kk * 64 + (d - 64)];
    else              v = Wv1[kk * 16 + (d - 128)];
    g_WT[idx] = v;
}

// ---------------- fold We/be through the edge slice of WT ----------------
__global__ void prep_w2_kernel(const float* __restrict__ We,
                               const float* __restrict__ be) {
    int idx = blockIdx.x * blockDim.x + threadIdx.x;
    if (idx < 21 * OUTC) {
        int t = idx / OUTC, d = idx % OUTC;
        float acc = 0.f;
        for (int c = 0; c < 32; ++c)
            acc = fmaf(We[t * 32 + c], g_WT[(64 + c) * OUTC + d], acc);
        g_W2[idx] = acc;
    } else if (idx < 21 * OUTC + OUTC) {
        int d = idx - 21 * OUTC;
        float acc = 0.f;
        for (int c = 0; c < 32; ++c)
            acc = fmaf(be[c], g_WT[(64 + c) * OUTC + d], acc);
        g_b2[d] = acc;
    }
}

// ---------------- mask + compaction ----------------
__global__ void compact_kernel(const int* __restrict__ seq,
                               const float* __restrict__ xyz,
                               const void* __restrict__ aamask) {
    __shared__ int s_scan[1024];
    __shared__ int s_nz_off4;
    __shared__ int s_f_ok;
    __shared__ int s_f_one;
    int tid = threadIdx.x;
    if (tid == 0) { s_nz_off4 = 0; s_f_ok = 1; s_f_one = 0; }
    __syncthreads();

    const unsigned char* am8  = (const unsigned char*)aamask;
    const int*           am32 = (const int*)aamask;
    const float*         amf  = (const float*)aamask;
    const int NA = 21 * A_ATOM;

    for (int p = tid; p < NA; p += 1024)
        if ((p & 3) && am8[p]) atomicOr(&s_nz_off4, 1);
    for (int wi = tid; wi < NA / 4; wi += 1024) {
        float f = amf[wi];
        if (!(f == 0.0f || f == 1.0f)) atomicAnd(&s_f_ok, 0);
        if (f == 1.0f) atomicOr(&s_f_one, 1);
    }
    __syncthreads();
    int mode = (!s_nz_off4) ? 0 : ((s_f_ok && s_f_one) ? 2 : 1);

    int base = tid * 9;
    unsigned char f[9];
    int cnt = 0;
#pragma unroll
    for (int i = 0; i < 9; ++i) {
        int m = base + i;
        int l = m / A_ATOM, a = m % A_ATOM;
        int q = seq[l] * A_ATOM + a;
        int v;
        if (mode == 0)      v = am32[q];
        else if (mode == 1) v = (int)am8[q];
        else                v = (amf[q] != 0.0f);
        f[i] = (v != 0);
        cnt += f[i];
    }
    s_scan[tid] = cnt;
    __syncthreads();
    for (int off = 1; off < 1024; off <<= 1) {
        int v = 0;
        if (tid >= off) v = s_scan[tid - off];
        __syncthreads();
        s_scan[tid] += v;
        __syncthreads();
    }
    int pos = s_scan[tid] - cnt;
#pragma unroll
    for (int i = 0; i < 9; ++i) {
        int m = base + i;
        if (f[i]) {
            g_midx[pos] = m;
            g_cxyz[pos] = make_float4(xyz[m * 3], xyz[m * 3 + 1], xyz[m * 3 + 2],
                                      __int_as_float(m));
            pos++;
        }
    }
    if (tid == 1023) g_nM = s_scan[1023];
}

// ---------------- per-atom P = state@W_state and q = qin@Wq ----------------
__global__ void __launch_bounds__(144) pq_kernel(const float* __restrict__ state,
                                                 const float* __restrict__ grads,
                                                 const float* __restrict__ Wq) {
    __shared__ float s_st[4][64];
    __shared__ float s_nr[4][3];
    int nM = g_nM;
    int base = blockIdx.x * 4;
    if (base >= nM) return;
    int tid = threadIdx.x;
    int nhere = min(4, nM - base);

    for (int i = tid; i < 4 * 64; i += 144) {
        int a = i >> 6, k = i & 63;
        if (a < nhere) s_st[a][k] = state[g_midx[base + a] * 64 + k];
    }
    if (tid < 12) {
        int a = tid >> 2;          // use only tid giving a<4, c<3 layout: a=tid/3
    }
    if (tid < 12) {
        int a = tid / 3, c = tid % 3;
        if (a < nhere) {
            int m = g_midx[base + a];
            float s = EPSF;
#pragma unroll
            for (int dd = 0; dd < 3; ++dd) {
                float v = grads[(c * M_ATOMS + m) * 3 + dd];
                s = fmaf(v, v, s);
            }
            s_nr[a][c] = sqrtf(s);
        }
    }
    __syncthreads();

    {
        float acc0 = 0.f, acc1 = 0.f, acc2 = 0.f, acc3 = 0.f;
        for (int k = 0; k < 64; ++k) {
            float wv = g_WT[k * OUTC + tid];
            acc0 = fmaf(s_st[0][k], wv, acc0);
            acc1 = fmaf(s_st[1][k], wv, acc1);
            acc2 = fmaf(s_st[2][k], wv, acc2);
            acc3 = fmaf(s_st[3][k], wv, acc3);
        }
        float accs[4] = {acc0, acc1, acc2, acc3};
        for (int a = 0; a < nhere; ++a)
            g_P[g_midx[base + a] * OUTC + tid] = accs[a];
    }
    if (tid < 64) {
        for (int a = 0; a < nhere; ++a) {
            float acc = 0.f;
            for (int k = 0; k < 64; ++k)
                acc = fmaf(s_st[a][k], Wq[k * 64 + tid], acc);
#pragma unroll
            for (int c = 0; c < KC; ++c)
                acc = fmaf(s_nr[a][c], Wq[(64 + c) * 64 + tid], acc);
            g_Qv[g_midx[base + a] * 64 + tid] = acc;
        }
    }
}

// ---------------- exact top-24: threshold-collect + small select ----------------
__device__ __forceinline__ unsigned long long knn_pack(float d, int j) {
    return ((unsigned long long)__float_as_uint(d) << 32) | (unsigned)j;
}

__global__ void __launch_bounds__(128) knn_kernel(void) {
    __shared__ float s_bd[4][KNN_CAP];
    __shared__ int   s_bi[4][KNN_CAP];
    int w    = threadIdx.x >> 5;
    int lane = threadIdx.x & 31;
    int qi   = blockIdx.x * 4 + w;
    int nM   = g_nM;
    if (qi >= nM) return;
    int m = g_midx[qi];
    float4 me = g_cxyz[qi];
    unsigned lmask = (1u << lane) - 1u;
    int target = min(K_NB, nM - 1);

    // ---- sample: 3rd smallest of first 64 candidates ----
    float da, db;
    {
        int j = lane;
        da = BIGF;
        if (j < nM && j != qi) {
            float4 c = g_cxyz[j];
            float dx = c.x - me.x, dy = c.y - me.y, dz = c.z - me.z;
            da = dx * dx + dy * dy + dz * dz;
        }
        j = 32 + lane;
        db = BIGF;
        if (j < nM && j != qi) {
            float4 c = g_cxyz[j];
            float dx = c.x - me.x, dy = c.y - me.y, dz = c.z - me.z;
            db = dx * dx + dy * dy + dz * dz;
        }
    }
    float T;
    {
        float a = da, b = db;
        float m3 = BIGF;
        for (int r = 0; r < 3; ++r) {
            float v = fminf(a, b);
#pragma unroll
            for (int off = 16; off; off >>= 1)
                v = fminf(v, __shfl_xor_sync(FULLW, v, off));
            m3 = v;
            if (a == v) a = BIGF;
            if (b == v) b = BIGF;
        }
        T = fminf(m3 * 1.0f, BIGF * 0.4f);
    }

    // ---- collect all d2 <= T (retry with adjusted T) ----
    int cnt = 0;
    bool valid = false;
    for (int attempt = 0; attempt < 12; ++attempt) {
        cnt = 0;
        for (int j0 = 0; j0 < nM; j0 += 32) {
            int j = j0 + lane;
            float d2 = BIGF;
            if (j < nM && j != qi) {
                float4 c = g_cxyz[j];
                float dx = c.x - me.x, dy = c.y - me.y, dz = c.z - me.z;
                d2 = dx * dx + dy * dy + dz * dz;
            }
            bool p = (d2 <= T);
            unsigned ball = __ballot_sync(FULLW, p);
            if (p) {
                int pos = cnt + __popc(ball & lmask);
                if (pos < KNN_CAP) { s_bd[w][pos] = d2; s_bi[w][pos] = j; }
            }
            cnt += __popc(ball);
            if (cnt > KNN_CAP) break;
        }
        if (cnt >= target && cnt <= KNN_CAP) { valid = true; break; }
        if (cnt < target) T = fminf(T * 4.0f, BIGF * 0.4f);
        else              T = T * 0.35f;
    }
    __syncwarp();

    if (valid) {
        unsigned long long last = 0ull;
        for (int r = 0; r < K_NB; ++r) {
            unsigned long long best = ~0ull;
            for (int t = lane; t < cnt; t += 32) {
                unsigned long long p = knn_pack(s_bd[w][t], s_bi[w][t]);
                if (p >= last && p < best) best = p;
            }
#pragma unroll
            for (int off = 16; off; off >>= 1) {
                unsigned long long o = __shfl_xor_sync(FULLW, best, off);
                if (o < best) best = o;
            }
            if (lane == r) {
                float d = __uint_as_float((unsigned)(best >> 32));
                g_knn[m * K_NB + r] =
                    (best != ~0ull && d < BIGF * 0.5f) ? g_midx[(unsigned)best & 0xffffffffu] : m;
            }
            last = best + 1ull;
        }
    } else {
        // exact fallback: 24 rounds of global argmin with ascending packed keys
        unsigned long long last = 0ull;
        for (int r = 0; r < K_NB; ++r) {
            unsigned long long best = ~0ull;
            for (int j = lane; j < nM; j += 32) {
                float d2 = BIGF;
                if (j != qi) {
                    float4 c = g_cxyz[j];
                    float dx = c.x - me.x, dy = c.y - me.y, dz = c.z - me.z;
                    d2 = dx * dx + dy * dy + dz * dz;
                }
                unsigned long long p = knn_pack(d2, j);
                if (p >= last && p < best) best = p;
            }
#pragma unroll
            for (int off = 16; off; off >>= 1) {
                unsigned long long o = __shfl_xor_sync(FULLW, best, off);
                if (o < best) best = o;
            }
            if (lane == r) {
                float d = __uint_as_float((unsigned)(best >> 32));
                g_knn[m * K_NB + r] =
                    (best != ~0ull && d < BIGF * 0.5f) ? g_midx[(unsigned)best & 0xffffffffu] : m;
            }
            last = best + 1ull;
        }
    }
}

// ---------------- per-atom edge attention (decomposed) ----------------
__global__ void __launch_bounds__(160) attn_kernel(
    const int* __restrict__ seq, const float* __restrict__ xyz,
    const int* __restrict__ num_bonds, const float* __restrict__ state,
    const float* __restrict__ grads,
    const float* __restrict__ Wo0, const float* __restrict__ Wself,
    const float* __restrict__ b0, float* __restrict__ out) {
    if (blockIdx.x >= g_nM) return;
    int m = g_midx[blockIdx.x];
    int tid = threadIdx.x;

    __shared__ float s_kv[K_NB][OUTC + 1];
    __shared__ float s_q[64];
    __shared__ float s_node[64];
    __shared__ float s_rbf[K_NB][RBF_N];
    __shared__ float s_dirv[K_NB][3];
    __shared__ float s_l1j[K_NB][KC][3];
    __shared__ float s_inv[K_NB][KC];
    __shared__ int   s_bond[K_NB];
    __shared__ float s_logit[HEADS][K_NB];
    __shared__ float s_attn[HEADS][K_NB];
    __shared__ float s_o0[64];
    __shared__ float s_coef[K_NB][4];
    __shared__ float s_vm[K_NB][3];
    __shared__ int   s_idx[K_NB];
    __shared__ float s_ok[K_NB];

    // ---- phase 0: node/q loads, per-edge geometry ----
    if (tid < 64) {
        s_node[tid] = state[m * 64 + tid];
    } else if (tid < 128) {
        s_q[tid - 64] = g_Qv[m * 64 + (tid - 64)];
    } else if (tid < 128 + K_NB) {
        int e = tid - 128;
        int j = g_knn[m * K_NB + e];
        s_idx[e] = j;
        float rx = xyz[j * 3]     - xyz[m * 3];
        float ry = xyz[j * 3 + 1] - xyz[m * 3 + 1];
        float rz = xyz[j * 3 + 2] - xyz[m * 3 + 2];
        float d2 = rx * rx + ry * ry + rz * rz;
        float dist = sqrtf(d2 + EPSF);
        float inv_d = 1.f / dist;
        float dvx = rx * inv_d, dvy = ry * inv_d, dvz = rz * inv_d;
        s_dirv[e][0] = dvx; s_dirv[e][1] = dvy; s_dirv[e][2] = dvz;
        s_ok[e] = (j != m) ? 1.f : 0.f;
#pragma unroll
        for (int c = 0; c < KC; ++c) {
            float lx = grads[(c * M_ATOMS + j) * 3 + 0];
            float ly = grads[(c * M_ATOMS + j) * 3 + 1];
            float lz = grads[(c * M_ATOMS + j) * 3 + 2];
            s_l1j[e][c][0] = lx; s_l1j[e][c][1] = ly; s_l1j[e][c][2] = lz;
            s_inv[e][c] = lx * dvx + ly * dvy + lz * dvz;
        }
        int ri = m / A_ATOM, ai = m % A_ATOM;
        int rj = j / A_ATOM, aj = j % A_ATOM;
        int b = 0;
        if (rj == ri) b = num_bonds[(seq[ri] * A_ATOM + ai) * A_ATOM + aj];
        s_bond[e] = min(max(b, 0), MAXB);
#pragma unroll
        for (int t = 0; t < RBF_N; ++t) {
            float r = dist - 0.4f * (float)t;
            s_rbf[e][t] = __expf(-2.f * r * r);
        }
    }
    __syncthreads();

    // ---- phase 1: kv[e][d] = P[j] + bias2 + rbf@W2 + W2[16+b] + inv@Winv ----
    if (tid < OUTC) {
        int d = tid;
        float w2r[RBF_N];
#pragma unroll
        for (int t = 0; t < RBF_N; ++t) w2r[t] = g_W2[t * OUTC + d];
        float wb0 = g_W2[16 * OUTC + d];
        float wb1 = g_W2[17 * OUTC + d];
        float wb2 = g_W2[18 * OUTC + d];
        float wb3 = g_W2[19 * OUTC + d];
        float wb4 = g_W2[20 * OUTC + d];
        float wi0 = g_WT[96 * OUTC + d];
        float wi1 = g_WT[97 * OUTC + d];
        float wi2 = g_WT[98 * OUTC + d];
        float b2  = g_b2[d];
#pragma unroll 8
        for (int e = 0; e < K_NB; ++e) {
            int j = s_idx[e];
            float acc = b2 + g_P[j * OUTC + d];
#pragma unroll
            for (int t = 0; t < RBF_N; ++t)
                acc = fmaf(s_rbf[e][t], w2r[t], acc);
            int b = s_bond[e];
            float wb = wb0;
            if (b == 1) wb = wb1;
            else if (b == 2) wb = wb2;
            else if (b == 3) wb = wb3;
            else if (b == 4) wb = wb4;
            acc += wb;
            acc = fmaf(s_inv[e][0], wi0, acc);
            acc = fmaf(s_inv[e][1], wi1, acc);
            acc = fmaf(s_inv[e][2], wi2, acc);
            s_kv[e][d] = acc;
        }
    }
    __syncthreads();

    // ---- phase 3: logits ----
    if (tid < HEADS * K_NB) {
        int h = tid / K_NB, e = tid % K_NB;
        float acc = 0.f;
#pragma unroll
        for (int dh = 0; dh < DHD; ++dh)
            acc = fmaf(s_q[h * DHD + dh], s_kv[e][h * DHD + dh], acc);
        s_logit[h][e] = (s_ok[e] > 0.f) ? acc * 0.25f : -1e9f;
    }
    __syncthreads();

    // ---- phase 4: softmax ----
    {
        int w = tid >> 5, lane = tid & 31;
        if (w < HEADS) {
            float v = (lane < K_NB) ? s_logit[w][lane] : -1e30f;
            float mx = v;
            for (int off = 16; off > 0; off >>= 1)
                mx = fmaxf(mx, __shfl_xor_sync(FULLW, mx, off));
            float ex = (lane < K_NB) ? __expf(v - mx) : 0.f;
            float sm = ex;
            for (int off = 16; off > 0; off >>= 1)
                sm += __shfl_xor_sync(FULLW, sm, off);
            if (lane < K_NB) s_attn[w][lane] = ex / sm;
        }
    }
    __syncthreads();

    // ---- phase 5: o0, coef ----
    if (tid < 64) {
        int h = tid >> 4;
        float acc = 0.f;
#pragma unroll
        for (int e = 0; e < K_NB; ++e)
            acc = fmaf(s_attn[h][e], s_kv[e][64 + tid], acc);
        s_o0[tid] = acc;
    } else if (tid < 160) {
        int t = tid - 64;
        int e = t % K_NB, c = t / K_NB;
        float acc = 0.f;
#pragma unroll
        for (int h = 0; h < HEADS; ++h)
            acc = fmaf(s_attn[h][e], s_kv[e][128 + h * 4 + c], acc);
        s_coef[e][c] = acc;
    }
    __syncthreads();

    // ---- phase 6: out0 (state), vmsg ----
    if (tid < 64) {
        float acc = b0[tid];
        for (int i = 0; i < 64; ++i) {
            acc = fmaf(s_o0[i],   Wo0[i * 64 + tid],   acc);
            acc = fmaf(s_node[i], Wself[i * 64 + tid], acc);
        }
        out[M_ATOMS * 3 + m * 64 + tid] = acc;
    }
    if (tid >= 64 && tid < 64 + K_NB) {
        int e = tid - 64;
        float c0 = s_coef[e][0];
#pragma unroll
        for (int dd = 0; dd < 3; ++dd) {
            float v = c0 * s_dirv[e][dd];
#pragma unroll
            for (int c = 0; c < KC; ++c)
                v = fmaf(s_coef[e][c + 1], s_l1j[e][c][dd], v);
            s_vm[e][dd] = v;
        }
    }
    __syncthreads();

    // ---- phase 7: out1 (xyz shift) ----
    if (tid < 3) {
        float acc = 0.f;
#pragma unroll
        for (int e = 0; e < K_NB; ++e) acc += s_vm[e][tid];
        out[m * 3 + tid] = xyz[m * 3 + tid] + acc * 0.01f;
    }
}

// ---------------- launch ----------------
extern "C" void kernel_launch(void* const* d_in, const int* in_sizes, int n_in,
                              void* d_out, int out_size) {
    const int*   seq       = (const int*)d_in[0];
    const float* xyz       = (const float*)d_in[1];
    const void*  aamask    = d_in[2];
    const int*   num_bonds = (const int*)d_in[3];
    const float* state     = (const float*)d_in[4];
    const float* grads     = (const float*)d_in[5];
    int w = 6;
    if (n_in >= 16 && in_sizes[6] == 1) w = 7;
    const float* We    = (const float*)d_in[w + 0];
    const float* be    = (const float*)d_in[w + 1];
    const float* Wq    = (const float*)d_in[w + 2];
    const float* Wk    = (const float*)d_in[w + 3];
    const float* Wv0   = (const float*)d_in[w + 4];
    const float* Wv1   = (const float*)d_in[w + 5];
    const float* Wo0   = (const float*)d_in[w + 6];
    const float* Wself = (const float*)d_in[w + 7];
    const float* b0    = (const float*)d_in[w + 8];
    float* out = (float*)d_out;

    init_out_kernel<<<512, 256>>>(xyz, state, out);
    prep_wt_kernel<<<(KIN_DIM * OUTC + 255) / 256, 256>>>(Wk, Wv0, Wv1);
    prep_w2_kernel<<<(22 * OUTC + 255) / 256, 256>>>(We, be);
    compact_kernel<<<1, 1024>>>(seq, xyz, aamask);
    pq_kernel<<<(M_ATOMS + 3) / 4, 144>>>(state, grads, Wq);
    knn_kernel<<<(M_ATOMS + 3) / 4, 128>>>();
    attn_kernel<<<M_ATOMS, 160>>>(seq, xyz, num_bonds, state, grads,
                                  Wo0, Wself, b0, out);
}